// round 1
// baseline (speedup 1.0000x reference)
#include <cuda_runtime.h>
#include <cuda_bf16.h>
#include <cstdint>

#define NB 32
#define NN 1024
#define NM 1024
#define NITER 500

// ---------------- device scratch (allocation-free) ----------------
static __device__ __align__(128) __nv_bfloat16 g_K[(size_t)NB * NN * NM]; // 64 MB bf16
static __device__ __align__(16) float g_u[NB * NN];
static __device__ __align__(16) float g_v[NB * NM];
static __device__ __align__(16) float g_part[NB * NN]; // per-(b,n) partial of sum(C*T)

__device__ __forceinline__ void cluster_sync_() {
    asm volatile("barrier.cluster.arrive.aligned;\n\t"
                 "barrier.cluster.wait.aligned;" ::: "memory");
}

// ---------------- precompute: K = bf16(exp(-10*C)), u0 = 1 ----------------
__global__ void prep_kernel(const float4* __restrict__ C4) {
    const size_t total4 = (size_t)NB * NN * NM / 4;
    const size_t stride = (size_t)gridDim.x * blockDim.x;
    for (size_t i = (size_t)blockIdx.x * blockDim.x + threadIdx.x; i < total4; i += stride) {
        float4 c = C4[i];
        unsigned k0 = __bfloat16_as_ushort(__float2bfloat16(__expf(-10.0f * c.x)));
        unsigned k1 = __bfloat16_as_ushort(__float2bfloat16(__expf(-10.0f * c.y)));
        unsigned k2 = __bfloat16_as_ushort(__float2bfloat16(__expf(-10.0f * c.z)));
        unsigned k3 = __bfloat16_as_ushort(__float2bfloat16(__expf(-10.0f * c.w)));
        uint2 o;
        o.x = k0 | (k1 << 16);
        o.y = k2 | (k3 << 16);
        reinterpret_cast<uint2*>(g_K)[i] = o;
    }
    for (size_t j = (size_t)blockIdx.x * blockDim.x + threadIdx.x; j < (size_t)NB * NN; j += stride)
        g_u[j] = 1.0f;
}

// ---------------- persistent Sinkhorn iteration kernel ----------------
// grid = 128 CTAs, cluster (4,1,1): 4 CTAs per batch, co-resident by HW.
extern "C" __global__ void __cluster_dims__(4, 1, 1) __launch_bounds__(256, 1)
sink_iter(const float* __restrict__ d1, const float* __restrict__ d2) {
    __shared__ float s_vec[NM];       // u (phase A) / v (phase B)
    __shared__ float s_red[8 * 256];  // cross-warp column reduction

    const int b = blockIdx.x >> 2;
    const int cr = blockIdx.x & 3;
    const int tid = threadIdx.x;
    const int lane = tid & 31;
    const int warp = tid >> 5;

    const __nv_bfloat16* Kbatch = g_K + (size_t)b * NN * NM;
    const float* d1b = d1 + b * NN;
    const float* d2b = d2 + b * NM;
    const int mbase = cr * 256;
    const int nbase = cr * 256;

    for (int it = 0; it < NITER; ++it) {
        // ---- Phase A: v[mbase + 0..255] = d2 / (K^T u) ----
        for (int i = tid; i < NN; i += 256) s_vec[i] = __ldcg(&g_u[b * NN + i]);
        __syncthreads();
        {
            const __nv_bfloat16* Kc = Kbatch + mbase + lane * 8;
            float acc[8];
#pragma unroll
            for (int j = 0; j < 8; ++j) acc[j] = 0.0f;
#pragma unroll 4
            for (int n = warp; n < NN; n += 8) {
                uint4 kv = *reinterpret_cast<const uint4*>(Kc + (size_t)n * NM);
                float u = s_vec[n];
                acc[0] = fmaf(__int_as_float(kv.x << 16), u, acc[0]);
                acc[1] = fmaf(__int_as_float(kv.x & 0xffff0000u), u, acc[1]);
                acc[2] = fmaf(__int_as_float(kv.y << 16), u, acc[2]);
                acc[3] = fmaf(__int_as_float(kv.y & 0xffff0000u), u, acc[3]);
                acc[4] = fmaf(__int_as_float(kv.z << 16), u, acc[4]);
                acc[5] = fmaf(__int_as_float(kv.z & 0xffff0000u), u, acc[5]);
                acc[6] = fmaf(__int_as_float(kv.w << 16), u, acc[6]);
                acc[7] = fmaf(__int_as_float(kv.w & 0xffff0000u), u, acc[7]);
            }
#pragma unroll
            for (int j = 0; j < 8; ++j) s_red[warp * 256 + lane * 8 + j] = acc[j];
        }
        __syncthreads();
        {
            float s = 0.0f;
#pragma unroll
            for (int g = 0; g < 8; ++g) s += s_red[g * 256 + tid];
            float v = d2b[mbase + tid] / s;
            __stcg(&g_v[b * NM + mbase + tid], v);
        }
        __syncthreads();
        cluster_sync_();

        // ---- Phase B: u[nbase + 0..255] = d1 / (K v) ----
        for (int i = tid; i < NM; i += 256) s_vec[i] = __ldcg(&g_v[b * NM + i]);
        __syncthreads();
        {
            const int row0w = nbase + warp * 32;
            for (int g = 0; g < 8; ++g) {
                const int r0 = row0w + g * 4;
                const __nv_bfloat16* Kr = Kbatch + (size_t)r0 * NM + lane * 8;
                float a[4] = {0.0f, 0.0f, 0.0f, 0.0f};
#pragma unroll
                for (int k = 0; k < 4; ++k) {
                    const int c0 = k * 256 + lane * 8;
                    float4 va = *reinterpret_cast<const float4*>(&s_vec[c0]);
                    float4 vb = *reinterpret_cast<const float4*>(&s_vec[c0 + 4]);
#pragma unroll
                    for (int r = 0; r < 4; ++r) {
                        uint4 kv = *reinterpret_cast<const uint4*>(Kr + (size_t)r * NM + k * 256);
                        float ar = a[r];
                        ar = fmaf(__int_as_float(kv.x << 16), va.x, ar);
                        ar = fmaf(__int_as_float(kv.x & 0xffff0000u), va.y, ar);
                        ar = fmaf(__int_as_float(kv.y << 16), va.z, ar);
                        ar = fmaf(__int_as_float(kv.y & 0xffff0000u), va.w, ar);
                        ar = fmaf(__int_as_float(kv.z << 16), vb.x, ar);
                        ar = fmaf(__int_as_float(kv.z & 0xffff0000u), vb.y, ar);
                        ar = fmaf(__int_as_float(kv.w << 16), vb.z, ar);
                        ar = fmaf(__int_as_float(kv.w & 0xffff0000u), vb.w, ar);
                        a[r] = ar;
                    }
                }
#pragma unroll
                for (int off = 16; off; off >>= 1) {
#pragma unroll
                    for (int r = 0; r < 4; ++r) a[r] += __shfl_xor_sync(0xffffffffu, a[r], off);
                }
                if (lane < 4) {
                    float s = a[lane];
                    __stcg(&g_u[b * NN + r0 + lane], d1b[r0 + lane] / s);
                }
            }
        }
        __syncthreads();
        cluster_sync_();
    }
}

// ---------------- finalize: T = u * exp(-10C) * v (fp32), partial dists ----------------
// one block per (b, n) row; 128 threads x 8 elements
__global__ void __launch_bounds__(128) finalize_kernel(const float* __restrict__ C,
                                                       float* __restrict__ Tout) {
    const int bid = blockIdx.x;       // 0 .. 32767
    const int b = bid >> 10;
    const int n = bid & 1023;
    const float* Crow = C + ((size_t)b * NN + n) * NM;
    float* Trow = Tout + ((size_t)b * NN + n) * NM;
    const float u = g_u[b * NN + n];
    const int tid = threadIdx.x;

    float local = 0.0f;
#pragma unroll
    for (int k = 0; k < 2; ++k) {
        const int m = tid * 4 + k * 512;
        float4 cv = *reinterpret_cast<const float4*>(Crow + m);
        float4 vv = *reinterpret_cast<const float4*>(&g_v[b * NM + m]);
        float4 t;
        t.x = u * __expf(-10.0f * cv.x) * vv.x;
        t.y = u * __expf(-10.0f * cv.y) * vv.y;
        t.z = u * __expf(-10.0f * cv.z) * vv.z;
        t.w = u * __expf(-10.0f * cv.w) * vv.w;
        local += cv.x * t.x + cv.y * t.y + cv.z * t.z + cv.w * t.w;
        *reinterpret_cast<float4*>(Trow + m) = t;
    }

    __shared__ float sred[128];
    sred[tid] = local;
    __syncthreads();
#pragma unroll
    for (int s = 64; s; s >>= 1) {
        if (tid < s) sred[tid] += sred[tid + s];
        __syncthreads();
    }
    if (tid == 0) g_part[bid] = sred[0];
}

// deterministic second-stage reduction of dists
__global__ void __launch_bounds__(256) dists_kernel(float* __restrict__ out) {
    const int b = blockIdx.x;
    const int tid = threadIdx.x;
    __shared__ float sr[256];
    float s = 0.0f;
    for (int i = tid; i < NN; i += 256) s += g_part[b * NN + i];
    sr[tid] = s;
    __syncthreads();
#pragma unroll
    for (int k = 128; k; k >>= 1) {
        if (tid < k) sr[tid] += sr[tid + k];
        __syncthreads();
    }
    if (tid == 0) out[b] = sr[0];
}

// ---------------- launch ----------------
extern "C" void kernel_launch(void* const* d_in, const int* in_sizes, int n_in,
                              void* d_out, int out_size) {
    (void)in_sizes; (void)n_in; (void)out_size;
    const float* C = (const float*)d_in[0];
    const float* d1 = (const float*)d_in[1];
    const float* d2 = (const float*)d_in[2];

    float* out = (float*)d_out;
    float* out_dists = out;                                  // [32]
    float* out_C = out + NB;                                 // [32,1024,1024]
    float* out_T = out_C + (size_t)NB * NN * NM;             // [32,1024,1024]

    // C passthrough (D2D async copy is graph-capturable)
    cudaMemcpyAsync(out_C, C, (size_t)NB * NN * NM * sizeof(float),
                    cudaMemcpyDeviceToDevice);

    prep_kernel<<<2048, 256>>>(reinterpret_cast<const float4*>(C));
    sink_iter<<<NB * 4, 256>>>(d1, d2);
    finalize_kernel<<<NB * NN, 128>>>(C, out_T);
    dists_kernel<<<NB, 256>>>(out_dists);
}

// round 3
// speedup vs baseline: 51.4036x; 51.4036x over previous
#include <cuda_runtime.h>
#include <cuda_bf16.h>
#include <cstdint>

#define NB 32
#define NN 1024
#define NM 1024
#define NITER 500
#define CONV_TOL 1e-6f

// ---------------- device scratch (allocation-free) ----------------
static __device__ __align__(128) __nv_bfloat16 g_K[(size_t)NB * NN * NM]; // 64 MB bf16
static __device__ __align__(16) float g_u[NB * NN];
static __device__ __align__(16) float g_v[NB * NM];
static __device__ __align__(16) float g_part[NB * NN];
static __device__ __align__(16) int g_flag[NB * 4];

__device__ __forceinline__ void cluster_sync_() {
    asm volatile("barrier.cluster.arrive.aligned;\n\t"
                 "barrier.cluster.wait.aligned;" ::: "memory");
}

// ---------------- precompute: K = bf16(exp(-10*C)), u0 = 1, C passthrough ----------------
__global__ void prep_kernel(const float4* __restrict__ C4, float4* __restrict__ outC4) {
    const size_t total4 = (size_t)NB * NN * NM / 4;
    const size_t stride = (size_t)gridDim.x * blockDim.x;
    for (size_t i = (size_t)blockIdx.x * blockDim.x + threadIdx.x; i < total4; i += stride) {
        float4 c = C4[i];
        outC4[i] = c;  // fused C passthrough (saves a separate 128MB memcpy read)
        unsigned k0 = __bfloat16_as_ushort(__float2bfloat16(__expf(-10.0f * c.x)));
        unsigned k1 = __bfloat16_as_ushort(__float2bfloat16(__expf(-10.0f * c.y)));
        unsigned k2 = __bfloat16_as_ushort(__float2bfloat16(__expf(-10.0f * c.z)));
        unsigned k3 = __bfloat16_as_ushort(__float2bfloat16(__expf(-10.0f * c.w)));
        uint2 o;
        o.x = k0 | (k1 << 16);
        o.y = k2 | (k3 << 16);
        reinterpret_cast<uint2*>(g_K)[i] = o;
    }
    for (size_t j = (size_t)blockIdx.x * blockDim.x + threadIdx.x; j < (size_t)NB * NN; j += stride)
        g_u[j] = 1.0f;
}

// ---------------- persistent Sinkhorn iteration kernel ----------------
// grid = 128 CTAs x 512 threads, cluster (4,1,1): 4 CTAs per batch.
extern "C" __global__ void __cluster_dims__(4, 1, 1) __launch_bounds__(512, 1)
sink_iter(const float* __restrict__ d1, const float* __restrict__ d2) {
    __shared__ float s_vec[NM];        // u (phase A) / v (phase B)
    __shared__ float s_red[16 * 256];  // cross-warp column reduction
    __shared__ float s_uown[256];      // previous u of this CTA's slice (convergence check)
    __shared__ int s_flag;             // 1 = not converged this iter
    __shared__ int s_break;

    const int b = blockIdx.x >> 2;
    const int cr = blockIdx.x & 3;
    const int tid = threadIdx.x;
    const int lane = tid & 31;
    const int warp = tid >> 5;

    const __nv_bfloat16* Kbatch = g_K + (size_t)b * NN * NM;
    const float* d1b = d1 + b * NN;
    const float* d2b = d2 + b * NM;
    const int mbase = cr * 256;
    const int nbase = cr * 256;

    for (int it = 0; it < NITER; ++it) {
        // ---- Phase A: v[mbase + 0..255] = d2 / (K^T u) ----
        for (int i = tid; i < NN; i += 512) s_vec[i] = __ldcg(&g_u[b * NN + i]);
        __syncthreads();
        if (tid < 256) s_uown[tid] = s_vec[nbase + tid];
        if (tid == 0) s_flag = 0;
        {
            const __nv_bfloat16* Kc = Kbatch + mbase + lane * 8;
            float acc[8];
#pragma unroll
            for (int j = 0; j < 8; ++j) acc[j] = 0.0f;
            // 16 warps, each handles 64 rows; 4 independent loads per outer iter.
            for (int n = warp; n < NN; n += 64) {
                uint4 kv0 = *reinterpret_cast<const uint4*>(Kc + (size_t)(n) * NM);
                uint4 kv1 = *reinterpret_cast<const uint4*>(Kc + (size_t)(n + 16) * NM);
                uint4 kv2 = *reinterpret_cast<const uint4*>(Kc + (size_t)(n + 32) * NM);
                uint4 kv3 = *reinterpret_cast<const uint4*>(Kc + (size_t)(n + 48) * NM);
                float u0 = s_vec[n];
                float u1 = s_vec[n + 16];
                float u2 = s_vec[n + 32];
                float u3 = s_vec[n + 48];
#define FMA8(kv, uu)                                                         \
                acc[0] = fmaf(__int_as_float(kv.x << 16), uu, acc[0]);        \
                acc[1] = fmaf(__int_as_float(kv.x & 0xffff0000u), uu, acc[1]);\
                acc[2] = fmaf(__int_as_float(kv.y << 16), uu, acc[2]);        \
                acc[3] = fmaf(__int_as_float(kv.y & 0xffff0000u), uu, acc[3]);\
                acc[4] = fmaf(__int_as_float(kv.z << 16), uu, acc[4]);        \
                acc[5] = fmaf(__int_as_float(kv.z & 0xffff0000u), uu, acc[5]);\
                acc[6] = fmaf(__int_as_float(kv.w << 16), uu, acc[6]);        \
                acc[7] = fmaf(__int_as_float(kv.w & 0xffff0000u), uu, acc[7]);
                FMA8(kv0, u0)
                FMA8(kv1, u1)
                FMA8(kv2, u2)
                FMA8(kv3, u3)
            }
#pragma unroll
            for (int j = 0; j < 8; ++j) s_red[warp * 256 + lane * 8 + j] = acc[j];
        }
        __syncthreads();
        if (tid < 256) {
            float s = 0.0f;
#pragma unroll
            for (int g = 0; g < 16; ++g) s += s_red[g * 256 + tid];
            float v = d2b[mbase + tid] / s;
            __stcg(&g_v[b * NM + mbase + tid], v);
        }
        __syncthreads();
        cluster_sync_();

        // ---- Phase B: u[nbase + 0..255] = d1 / (K v) ----
        for (int i = tid; i < NM; i += 512) s_vec[i] = __ldcg(&g_v[b * NM + i]);
        __syncthreads();
        {
            const int row0w = nbase + warp * 16;
#pragma unroll
            for (int g = 0; g < 4; ++g) {
                const int r0 = row0w + g * 4;
                const __nv_bfloat16* Kr = Kbatch + (size_t)r0 * NM + lane * 8;
                float a[4] = {0.0f, 0.0f, 0.0f, 0.0f};
#pragma unroll
                for (int k = 0; k < 4; ++k) {
                    const int c0 = k * 256 + lane * 8;
                    float4 va = *reinterpret_cast<const float4*>(&s_vec[c0]);
                    float4 vb = *reinterpret_cast<const float4*>(&s_vec[c0 + 4]);
                    uint4 kq0 = *reinterpret_cast<const uint4*>(Kr + (size_t)0 * NM + k * 256);
                    uint4 kq1 = *reinterpret_cast<const uint4*>(Kr + (size_t)1 * NM + k * 256);
                    uint4 kq2 = *reinterpret_cast<const uint4*>(Kr + (size_t)2 * NM + k * 256);
                    uint4 kq3 = *reinterpret_cast<const uint4*>(Kr + (size_t)3 * NM + k * 256);
#define ROWFMA(r, kv)                                                  \
                    {                                                   \
                        float ar = a[r];                                \
                        ar = fmaf(__int_as_float(kv.x << 16), va.x, ar);\
                        ar = fmaf(__int_as_float(kv.x & 0xffff0000u), va.y, ar);\
                        ar = fmaf(__int_as_float(kv.y << 16), va.z, ar);\
                        ar = fmaf(__int_as_float(kv.y & 0xffff0000u), va.w, ar);\
                        ar = fmaf(__int_as_float(kv.z << 16), vb.x, ar);\
                        ar = fmaf(__int_as_float(kv.z & 0xffff0000u), vb.y, ar);\
                        ar = fmaf(__int_as_float(kv.w << 16), vb.z, ar);\
                        ar = fmaf(__int_as_float(kv.w & 0xffff0000u), vb.w, ar);\
                        a[r] = ar;                                      \
                    }
                    ROWFMA(0, kq0)
                    ROWFMA(1, kq1)
                    ROWFMA(2, kq2)
                    ROWFMA(3, kq3)
                }
#pragma unroll
                for (int off = 16; off; off >>= 1) {
#pragma unroll
                    for (int r = 0; r < 4; ++r) a[r] += __shfl_xor_sync(0xffffffffu, a[r], off);
                }
                if (lane < 4) {
                    float un = d1b[r0 + lane] / a[lane];
                    __stcg(&g_u[b * NN + r0 + lane], un);
                    float uold = s_uown[warp * 16 + g * 4 + lane];
                    if (fabsf(un - uold) > CONV_TOL * fabsf(un)) s_flag = 1;
                }
            }
        }
        __syncthreads();
        if (tid == 0) __stcg(&g_flag[blockIdx.x], s_flag);
        cluster_sync_();
        if (tid == 0) {
            int base = (b << 2);
            int f = __ldcg(&g_flag[base]) | __ldcg(&g_flag[base + 1]) |
                    __ldcg(&g_flag[base + 2]) | __ldcg(&g_flag[base + 3]);
            s_break = (f == 0);
        }
        __syncthreads();
        if (s_break) break;
    }
}

// ---------------- finalize: T = u * exp(-10C) * v (fp32), partial dists ----------------
__global__ void __launch_bounds__(128) finalize_kernel(const float* __restrict__ C,
                                                       float* __restrict__ Tout) {
    const int bid = blockIdx.x;
    const int b = bid >> 10;
    const int n = bid & 1023;
    const float* Crow = C + ((size_t)b * NN + n) * NM;
    float* Trow = Tout + ((size_t)b * NN + n) * NM;
    const float u = g_u[b * NN + n];
    const int tid = threadIdx.x;

    float local = 0.0f;
#pragma unroll
    for (int k = 0; k < 2; ++k) {
        const int m = tid * 4 + k * 512;
        float4 cv = *reinterpret_cast<const float4*>(Crow + m);
        float4 vv = *reinterpret_cast<const float4*>(&g_v[b * NM + m]);
        float4 t;
        t.x = u * __expf(-10.0f * cv.x) * vv.x;
        t.y = u * __expf(-10.0f * cv.y) * vv.y;
        t.z = u * __expf(-10.0f * cv.z) * vv.z;
        t.w = u * __expf(-10.0f * cv.w) * vv.w;
        local += cv.x * t.x + cv.y * t.y + cv.z * t.z + cv.w * t.w;
        *reinterpret_cast<float4*>(Trow + m) = t;
    }

    __shared__ float sred[128];
    sred[tid] = local;
    __syncthreads();
#pragma unroll
    for (int s = 64; s; s >>= 1) {
        if (tid < s) sred[tid] += sred[tid + s];
        __syncthreads();
    }
    if (tid == 0) g_part[bid] = sred[0];
}

__global__ void __launch_bounds__(256) dists_kernel(float* __restrict__ out) {
    const int b = blockIdx.x;
    const int tid = threadIdx.x;
    __shared__ float sr[256];
    float s = 0.0f;
    for (int i = tid; i < NN; i += 256) s += g_part[b * NN + i];
    sr[tid] = s;
    __syncthreads();
#pragma unroll
    for (int k = 128; k; k >>= 1) {
        if (tid < k) sr[tid] += sr[tid + k];
        __syncthreads();
    }
    if (tid == 0) out[b] = sr[0];
}

// ---------------- launch ----------------
extern "C" void kernel_launch(void* const* d_in, const int* in_sizes, int n_in,
                              void* d_out, int out_size) {
    (void)in_sizes; (void)n_in; (void)out_size;
    const float* C = (const float*)d_in[0];
    const float* d1 = (const float*)d_in[1];
    const float* d2 = (const float*)d_in[2];

    float* out = (float*)d_out;
    float* out_dists = out;                                  // [32]
    float* out_C = out + NB;                                 // [32,1024,1024]
    float* out_T = out_C + (size_t)NB * NN * NM;             // [32,1024,1024]

    prep_kernel<<<2048, 256>>>(reinterpret_cast<const float4*>(C),
                               reinterpret_cast<float4*>(out_C));
    sink_iter<<<NB * 4, 512>>>(d1, d2);
    finalize_kernel<<<NB * NN, 128>>>(C, out_T);
    dists_kernel<<<NB, 256>>>(out_dists);
}

// round 6
// speedup vs baseline: 55.4954x; 1.0796x over previous
#include <cuda_runtime.h>
#include <cuda_bf16.h>
#include <cstdint>

#define NB 32
#define NN 1024
#define NM 1024
#define NITER 500
#define CONV_TOL 2e-5f

// ---------------- device scratch (allocation-free) ----------------
static __device__ __align__(128) __nv_bfloat16 g_K[(size_t)NB * NN * NM]; // 64 MB bf16
static __device__ __align__(16) float g_u[NB * NN];
static __device__ __align__(16) float g_v[NB * NM];
static __device__ __align__(16) float g_part[NB * NN];
static __device__ __align__(16) int g_flag[NB * 4];

__device__ __forceinline__ void cluster_sync_() {
    asm volatile("barrier.cluster.arrive.aligned;\n\t"
                 "barrier.cluster.wait.aligned;" ::: "memory");
}

// ---------------- precompute: K = bf16(exp(-10*C)), u0 = 1, C passthrough ----------------
__global__ void prep_kernel(const float4* __restrict__ C4, float4* __restrict__ outC4) {
    const size_t total4 = (size_t)NB * NN * NM / 4;
    const size_t stride = (size_t)gridDim.x * blockDim.x;
    for (size_t i = (size_t)blockIdx.x * blockDim.x + threadIdx.x; i < total4; i += stride) {
        float4 c = C4[i];
        outC4[i] = c;  // fused C passthrough (saves a separate 128MB memcpy read)
        unsigned k0 = __bfloat16_as_ushort(__float2bfloat16(__expf(-10.0f * c.x)));
        unsigned k1 = __bfloat16_as_ushort(__float2bfloat16(__expf(-10.0f * c.y)));
        unsigned k2 = __bfloat16_as_ushort(__float2bfloat16(__expf(-10.0f * c.z)));
        unsigned k3 = __bfloat16_as_ushort(__float2bfloat16(__expf(-10.0f * c.w)));
        uint2 o;
        o.x = k0 | (k1 << 16);
        o.y = k2 | (k3 << 16);
        reinterpret_cast<uint2*>(g_K)[i] = o;
    }
    for (size_t j = (size_t)blockIdx.x * blockDim.x + threadIdx.x; j < (size_t)NB * NN; j += stride)
        g_u[j] = 1.0f;
}

// ---------------- persistent Sinkhorn iteration kernel ----------------
// grid = 128 CTAs x 512 threads, cluster (4,1,1): 4 CTAs per batch.
extern "C" __global__ void __cluster_dims__(4, 1, 1) __launch_bounds__(512, 1)
sink_iter(const float* __restrict__ d1, const float* __restrict__ d2) {
    __shared__ float s_vec[NM];        // u (phase A) / v (phase B)
    __shared__ float s_red[16 * 256];  // cross-warp column reduction
    __shared__ float s_uown[256];      // previous u of this CTA's slice (convergence check)
    __shared__ int s_flag;             // 1 = not converged this iter
    __shared__ int s_break;

    const int b = blockIdx.x >> 2;
    const int cr = blockIdx.x & 3;
    const int tid = threadIdx.x;
    const int lane = tid & 31;
    const int warp = tid >> 5;

    const __nv_bfloat16* Kbatch = g_K + (size_t)b * NN * NM;
    const float* d1b = d1 + b * NN;
    const float* d2b = d2 + b * NM;
    const int mbase = cr * 256;
    const int nbase = cr * 256;

    for (int it = 0; it < NITER; ++it) {
        // ---- Phase A: v[mbase + 0..255] = d2 / (K^T u) ----
        for (int i = tid; i < NN; i += 512) s_vec[i] = __ldcg(&g_u[b * NN + i]);
        __syncthreads();
        if (tid < 256) s_uown[tid] = s_vec[nbase + tid];
        if (tid == 0) s_flag = 0;
        {
            const __nv_bfloat16* Kc = Kbatch + mbase + lane * 8;
            float acc[8];
#pragma unroll
            for (int j = 0; j < 8; ++j) acc[j] = 0.0f;
            // 16 warps, each handles 64 rows; 4 independent loads per outer iter.
            for (int n = warp; n < NN; n += 64) {
                uint4 kv0 = *reinterpret_cast<const uint4*>(Kc + (size_t)(n) * NM);
                uint4 kv1 = *reinterpret_cast<const uint4*>(Kc + (size_t)(n + 16) * NM);
                uint4 kv2 = *reinterpret_cast<const uint4*>(Kc + (size_t)(n + 32) * NM);
                uint4 kv3 = *reinterpret_cast<const uint4*>(Kc + (size_t)(n + 48) * NM);
                float u0 = s_vec[n];
                float u1 = s_vec[n + 16];
                float u2 = s_vec[n + 32];
                float u3 = s_vec[n + 48];
#define FMA8(kv, uu)                                                         \
                acc[0] = fmaf(__int_as_float(kv.x << 16), uu, acc[0]);        \
                acc[1] = fmaf(__int_as_float(kv.x & 0xffff0000u), uu, acc[1]);\
                acc[2] = fmaf(__int_as_float(kv.y << 16), uu, acc[2]);        \
                acc[3] = fmaf(__int_as_float(kv.y & 0xffff0000u), uu, acc[3]);\
                acc[4] = fmaf(__int_as_float(kv.z << 16), uu, acc[4]);        \
                acc[5] = fmaf(__int_as_float(kv.z & 0xffff0000u), uu, acc[5]);\
                acc[6] = fmaf(__int_as_float(kv.w << 16), uu, acc[6]);        \
                acc[7] = fmaf(__int_as_float(kv.w & 0xffff0000u), uu, acc[7]);
                FMA8(kv0, u0)
                FMA8(kv1, u1)
                FMA8(kv2, u2)
                FMA8(kv3, u3)
            }
#pragma unroll
            for (int j = 0; j < 8; ++j) s_red[warp * 256 + lane * 8 + j] = acc[j];
        }
        __syncthreads();
        if (tid < 256) {
            float s = 0.0f;
#pragma unroll
            for (int g = 0; g < 16; ++g) s += s_red[g * 256 + tid];
            float v = d2b[mbase + tid] / s;
            __stcg(&g_v[b * NM + mbase + tid], v);
        }
        __syncthreads();
        cluster_sync_();

        // ---- Phase B: u[nbase + 0..255] = d1 / (K v) ----
        for (int i = tid; i < NM; i += 512) s_vec[i] = __ldcg(&g_v[b * NM + i]);
        __syncthreads();
        {
            const int row0w = nbase + warp * 16;
#pragma unroll
            for (int g = 0; g < 4; ++g) {
                const int r0 = row0w + g * 4;
                const __nv_bfloat16* Kr = Kbatch + (size_t)r0 * NM + lane * 8;
                float a[4] = {0.0f, 0.0f, 0.0f, 0.0f};
#pragma unroll
                for (int k = 0; k < 4; ++k) {
                    const int c0 = k * 256 + lane * 8;
                    float4 va = *reinterpret_cast<const float4*>(&s_vec[c0]);
                    float4 vb = *reinterpret_cast<const float4*>(&s_vec[c0 + 4]);
                    uint4 kq0 = *reinterpret_cast<const uint4*>(Kr + (size_t)0 * NM + k * 256);
                    uint4 kq1 = *reinterpret_cast<const uint4*>(Kr + (size_t)1 * NM + k * 256);
                    uint4 kq2 = *reinterpret_cast<const uint4*>(Kr + (size_t)2 * NM + k * 256);
                    uint4 kq3 = *reinterpret_cast<const uint4*>(Kr + (size_t)3 * NM + k * 256);
#define ROWFMA(r, kv)                                                  \
                    {                                                   \
                        float ar = a[r];                                \
                        ar = fmaf(__int_as_float(kv.x << 16), va.x, ar);\
                        ar = fmaf(__int_as_float(kv.x & 0xffff0000u), va.y, ar);\
                        ar = fmaf(__int_as_float(kv.y << 16), va.z, ar);\
                        ar = fmaf(__int_as_float(kv.y & 0xffff0000u), va.w, ar);\
                        ar = fmaf(__int_as_float(kv.z << 16), vb.x, ar);\
                        ar = fmaf(__int_as_float(kv.z & 0xffff0000u), vb.y, ar);\
                        ar = fmaf(__int_as_float(kv.w << 16), vb.z, ar);\
                        ar = fmaf(__int_as_float(kv.w & 0xffff0000u), vb.w, ar);\
                        a[r] = ar;                                      \
                    }
                    ROWFMA(0, kq0)
                    ROWFMA(1, kq1)
                    ROWFMA(2, kq2)
                    ROWFMA(3, kq3)
                }
#pragma unroll
                for (int off = 16; off; off >>= 1) {
#pragma unroll
                    for (int r = 0; r < 4; ++r) a[r] += __shfl_xor_sync(0xffffffffu, a[r], off);
                }
                if (lane < 4) {
                    float un = d1b[r0 + lane] / a[lane];
                    __stcg(&g_u[b * NN + r0 + lane], un);
                    float uold = s_uown[warp * 16 + g * 4 + lane];
                    if (fabsf(un - uold) > CONV_TOL * fabsf(un)) s_flag = 1;
                }
            }
        }
        __syncthreads();
        if (tid == 0) __stcg(&g_flag[blockIdx.x], s_flag);
        cluster_sync_();
        if (tid == 0) {
            int base = (b << 2);
            int f = __ldcg(&g_flag[base]) | __ldcg(&g_flag[base + 1]) |
                    __ldcg(&g_flag[base + 2]) | __ldcg(&g_flag[base + 3]);
            s_break = (f == 0);
        }
        __syncthreads();
        if (s_break) break;
    }
}

// ---------------- finalize: T = u * exp(-10C) * v (fp32), partial dists ----------------
__global__ void __launch_bounds__(128) finalize_kernel(const float* __restrict__ C,
                                                       float* __restrict__ Tout) {
    const int bid = blockIdx.x;
    const int b = bid >> 10;
    const int n = bid & 1023;
    const float* Crow = C + ((size_t)b * NN + n) * NM;
    float* Trow = Tout + ((size_t)b * NN + n) * NM;
    const float u = g_u[b * NN + n];
    const int tid = threadIdx.x;

    float local = 0.0f;
#pragma unroll
    for (int k = 0; k < 2; ++k) {
        const int m = tid * 4 + k * 512;
        float4 cv = *reinterpret_cast<const float4*>(Crow + m);
        float4 vv = *reinterpret_cast<const float4*>(&g_v[b * NM + m]);
        float4 t;
        t.x = u * __expf(-10.0f * cv.x) * vv.x;
        t.y = u * __expf(-10.0f * cv.y) * vv.y;
        t.z = u * __expf(-10.0f * cv.z) * vv.z;
        t.w = u * __expf(-10.0f * cv.w) * vv.w;
        local += cv.x * t.x + cv.y * t.y + cv.z * t.z + cv.w * t.w;
        *reinterpret_cast<float4*>(Trow + m) = t;
    }

    __shared__ float sred[128];
    sred[tid] = local;
    __syncthreads();
#pragma unroll
    for (int s = 64; s; s >>= 1) {
        if (tid < s) sred[tid] += sred[tid + s];
        __syncthreads();
    }
    if (tid == 0) g_part[bid] = sred[0];
}

__global__ void __launch_bounds__(256) dists_kernel(float* __restrict__ out) {
    const int b = blockIdx.x;
    const int tid = threadIdx.x;
    __shared__ float sr[256];
    float s = 0.0f;
    for (int i = tid; i < NN; i += 256) s += g_part[b * NN + i];
    sr[tid] = s;
    __syncthreads();
#pragma unroll
    for (int k = 128; k; k >>= 1) {
        if (tid < k) sr[tid] += sr[tid + k];
        __syncthreads();
    }
    if (tid == 0) out[b] = sr[0];
}

// ---------------- launch ----------------
extern "C" void kernel_launch(void* const* d_in, const int* in_sizes, int n_in,
                              void* d_out, int out_size) {
    (void)in_sizes; (void)n_in; (void)out_size;
    const float* C = (const float*)d_in[0];
    const float* d1 = (const float*)d_in[1];
    const float* d2 = (const float*)d_in[2];

    float* out = (float*)d_out;
    float* out_dists = out;                                  // [32]
    float* out_C = out + NB;                                 // [32,1024,1024]
    float* out_T = out_C + (size_t)NB * NN * NM;             // [32,1024,1024]

    prep_kernel<<<2048, 256>>>(reinterpret_cast<const float4*>(C),
                               reinterpret_cast<float4*>(out_C));
    sink_iter<<<NB * 4, 512>>>(d1, d2);
    finalize_kernel<<<NB * NN, 128>>>(C, out_T);
    dists_kernel<<<NB, 256>>>(out_dists);
}